// round 14
// baseline (speedup 1.0000x reference)
#include <cuda_runtime.h>
#include <cstdint>
#include <cstddef>

#define BB 1024
#define SS 1024
#define FF 36
#define HH 20
#define FULLMASK 0xffffffffu

typedef unsigned long long ull;

__device__ float g_h[BB * HH];
__device__ int g_oh64;

// ---------------------------------------------------------------------------
// f32x2 packed helpers (packing = 2 adjacent K-elements of one batch)
// ---------------------------------------------------------------------------
__device__ __forceinline__ ull fma2(ull a, ull b, ull c) {
    ull d; asm("fma.rn.f32x2 %0,%1,%2,%3;" : "=l"(d) : "l"(a), "l"(b), "l"(c)); return d;
}
__device__ __forceinline__ ull pk2(float a, float b) {
    ull r; asm("mov.b64 %0,{%1,%2};" : "=l"(r) : "f"(a), "f"(b)); return r;
}
__device__ __forceinline__ float hadd2(ull v) {
    float lo, hi; asm("mov.b64 {%0,%1},%2;" : "=f"(lo), "=f"(hi) : "l"(v));
    return lo + hi;
}
__device__ __forceinline__ ull add2(ull a, ull b) {
    ull d; asm("add.rn.f32x2 %0,%1,%2;" : "=l"(d) : "l"(a), "l"(b)); return d;
}
__device__ __forceinline__ float tanh_hw(float x) {
    float y; asm("tanh.approx.f32 %0,%1;" : "=f"(y) : "f"(x)); return y;
}
__device__ __forceinline__ void cpasync16(uint32_t saddr, const void* g) {
    asm volatile("cp.async.cg.shared.global [%0], [%1], 16;" :: "r"(saddr), "l"(g));
}
#define CP_COMMIT() asm volatile("cp.async.commit_group;" ::: "memory")
#define CP_WAIT3()  asm volatile("cp.async.wait_group 3;" ::: "memory")

// ---------------------------------------------------------------------------
__global__ void detect_kernel(const int* __restrict__ oh) {
    if (threadIdx.x == 0 && blockIdx.x == 0) {
        int z = 1;
        for (int i = 1; i < 64; i += 2)
            if (oh[i] != 0) { z = 0; break; }
        g_oh64 = z;
    }
}

__global__ void embed_kernel(const float* __restrict__ x,
                             const int* __restrict__ oh,
                             const float* __restrict__ e0,
                             const float* __restrict__ e1,
                             const float* __restrict__ e2,
                             const float* __restrict__ e3,
                             float* __restrict__ origin) {
    int idx = blockIdx.x * blockDim.x + threadIdx.x;
    if (idx >= BB * SS) return;
    int i0, i1, i2, i3;
    if (g_oh64) {
        const int* p = oh + (size_t)idx * 8;
        i0 = p[0]; i1 = p[2]; i2 = p[4]; i3 = p[6];
    } else {
        int4 o = reinterpret_cast<const int4*>(oh)[idx];
        i0 = o.x; i1 = o.y; i2 = o.z; i3 = o.w;
    }
    const float4* xr = reinterpret_cast<const float4*>(x + (size_t)idx * 12);
    float4* out = reinterpret_cast<float4*>(origin + (size_t)idx * FF);
    out[0] = xr[0];
    out[1] = xr[1];
    out[2] = xr[2];
    out[3] = reinterpret_cast<const float4*>(e0)[i0];
    out[4] = reinterpret_cast<const float4*>(e1)[i1];
    const float4* e2p = reinterpret_cast<const float4*>(e2);
    out[5] = e2p[i2 * 2];
    out[6] = e2p[i2 * 2 + 1];
    const float4* e3p = reinterpret_cast<const float4*>(e3);
    out[7] = e3p[i3 * 2];
    out[8] = e3p[i3 * 2 + 1];
}

// ---------------------------------------------------------------------------
// Warp-per-batch GRU, same-unit mapping:
//   lanes 0..19 : slot0 = r row u (=l), slot1 = n row 40+u  -> r,n LOCAL
//   lanes 20..31: slot0 = z rows 20..31 (units 0..11)
//   lanes 20..27: slot1 = z rows 32..39 (units 12..19)
// Critical path: dots -> tanh(r) -> tanh(n) local; z arrives via one shfl
// that overlaps the r->n chain. Split accumulators halve the fma RAW chain.
// ---------------------------------------------------------------------------
struct WCtx {
    ull wx0[18], wx1[18];
    ull wh0[10], wh1[10];
    float b0c, b1i, b1h;
    bool isH;
    int l;
};

__device__ __forceinline__ void load_wctx(
    WCtx& C, int l,
    const float* __restrict__ Wih, const float* __restrict__ Whh,
    const float* __restrict__ bih, const float* __restrict__ bhh) {
    C.l = l;
    C.isH = (l < HH);
    int r0 = l;                                            // rows 0..31
    int r1 = C.isH ? (40 + l) : ((l < 28) ? (l + 12) : 59); // n rows / z rows 32..39
#pragma unroll
    for (int i = 0; i < 18; i++) {
        C.wx0[i] = pk2(Wih[r0 * FF + 2 * i], Wih[r0 * FF + 2 * i + 1]);
        C.wx1[i] = pk2(Wih[r1 * FF + 2 * i], Wih[r1 * FF + 2 * i + 1]);
    }
#pragma unroll
    for (int i = 0; i < 10; i++) {
        C.wh0[i] = pk2(Whh[r0 * HH + 2 * i], Whh[r0 * HH + 2 * i + 1]);
        C.wh1[i] = pk2(Whh[r1 * HH + 2 * i], Whh[r1 * HH + 2 * i + 1]);
    }
    C.b0c = bih[r0] + bhh[r0];
    if (C.isH) { C.b1i = bih[r1]; C.b1h = bhh[r1]; }
    else       { C.b1i = bih[r1] + bhh[r1]; C.b1h = 0.f; }
}

// One GRU cell: x-dot + h-dot from per-warp smem. Returns raw new h (l<20).
__device__ __forceinline__ float gru_cell_w(
    const WCtx& C, const float* __restrict__ xs, const float* __restrict__ hs,
    float hprev) {
    ull ax0a = 0, ax0b = 0, ax1a = 0, ax1b = 0;
    const ulonglong2* xv = reinterpret_cast<const ulonglong2*>(xs);
#pragma unroll
    for (int i = 0; i < 9; i++) {
        ulonglong2 v = xv[i];
        ax0a = fma2(C.wx0[2 * i], v.x, ax0a);
        ax0b = fma2(C.wx0[2 * i + 1], v.y, ax0b);
        ax1a = fma2(C.wx1[2 * i], v.x, ax1a);
        ax1b = fma2(C.wx1[2 * i + 1], v.y, ax1b);
    }
    ull ah0a = 0, ah0b = 0, ah1a = 0, ah1b = 0;
    const ulonglong2* hv = reinterpret_cast<const ulonglong2*>(hs);
#pragma unroll
    for (int i = 0; i < 5; i++) {
        ulonglong2 v = hv[i];
        ah0a = fma2(C.wh0[2 * i], v.x, ah0a);
        ah0b = fma2(C.wh0[2 * i + 1], v.y, ah0b);
        ah1a = fma2(C.wh1[2 * i], v.x, ah1a);
        ah1b = fma2(C.wh1[2 * i + 1], v.y, ah1b);
    }
    float sx0 = hadd2(add2(ax0a, ax0b));
    float sh0 = hadd2(add2(ah0a, ah0b));
    float sx1 = hadd2(add2(ax1a, ax1b));
    float sh1 = hadd2(add2(ah1a, ah1b));
    // slot0: sigmoid (r for lanes<20, z rows 20..31 for lanes 20..31)
    float sig0 = fmaf(0.5f, tanh_hw(0.5f * (sx0 + sh0 + C.b0c)), 0.5f);
    // slot1: n (local r!) for lanes<20; z rows 32..39 for lanes 20..27
    float argH = sx1 + C.b1i + sig0 * (sh1 + C.b1h);
    float argZ = 0.5f * (sx1 + sh1 + C.b1i);
    float t1 = tanh_hw(C.isH ? argH : argZ);
    float val1 = C.isH ? t1 : fmaf(0.5f, t1, 0.5f);
    // z gather for h-update (unit u = l < 20):
    float zA = __shfl_sync(FULLMASK, sig0, (20 + C.l) & 31);  // z row 20+u, u<12
    float zB = __shfl_sync(FULLMASK, val1, (8 + C.l) & 31);   // z row 20+u, u>=12
    float z = (C.l < 12) ? zA : zB;
    return fmaf(z, hprev - val1, val1);   // val1 = n (local) on h-lanes
}

// ---------------------------------------------------------------------------
// Encoder: warp per batch (8 warps/CTA); 4-slot x ring fed by cp.async
// (3 groups in flight).
// ---------------------------------------------------------------------------
__global__ void __launch_bounds__(256, 1) encoder_kernel(
    const float* __restrict__ xin,
    const float* __restrict__ Wih, const float* __restrict__ Whh,
    const float* __restrict__ bih, const float* __restrict__ bhh) {
    __shared__ __align__(16) float xring[8][4][FF];
    __shared__ __align__(16) float hbuf[8][2][HH];

    int tid = threadIdx.x;
    int w = tid >> 5, l = tid & 31;
    int b = blockIdx.x * 8 + w;

    WCtx C;
    load_wctx(C, l, Wih, Whh, bih, bhh);

    const float* xrow = xin + (size_t)b * SS * FF;
    float* xr_ = &xring[w][0][0];
    float* hb_ = &hbuf[w][0][0];
    uint32_t xr_s = (uint32_t)__cvta_generic_to_shared(xr_);

    bool ld = (l < 9);
#pragma unroll
    for (int s0 = 0; s0 < 3; s0++) {
        if (ld) cpasync16(xr_s + (uint32_t)(s0 * FF + l * 4) * 4,
                          xrow + (size_t)s0 * FF + l * 4);
        CP_COMMIT();
    }
    if (l < HH) hb_[l] = 0.f;

    float h = 0.f;
    for (int s = 0; s < SS; ++s) {
        if (ld && (s + 3 < SS))
            cpasync16(xr_s + (uint32_t)(((s + 3) & 3) * FF + l * 4) * 4,
                      xrow + (size_t)(s + 3) * FF + l * 4);
        CP_COMMIT();
        CP_WAIT3();          // group for slot s complete
        __syncwarp();
        int cur = s & 1;
        float hn = gru_cell_w(C, xr_ + (s & 3) * FF, hb_ + cur * HH, h);
        if (l < HH) { h = hn; hb_[(cur ^ 1) * HH + l] = hn; }
        __syncwarp();
    }
    if (l < HH) g_h[b * HH + l] = tanh_hw(h);
}

// ---------------------------------------------------------------------------
// Decoder: warp per batch (8 warps/CTA); gates -> tanh -> proj.
// proj: slot0 o=l (0..31), slot1 o=l+32 (l<4); Wfc rows K-packed in regs.
// ---------------------------------------------------------------------------
__global__ void __launch_bounds__(256, 1) decoder_kernel(
    const float* __restrict__ Wih, const float* __restrict__ Whh,
    const float* __restrict__ bih, const float* __restrict__ bhh,
    const float* __restrict__ Wfc, const float* __restrict__ bfc,
    float* __restrict__ out_xs) {
    __shared__ __align__(16) float xbuf[8][2][FF];
    __shared__ __align__(16) float hbuf[8][2][HH];

    int tid = threadIdx.x;
    int w = tid >> 5, l = tid & 31;
    int b = blockIdx.x * 8 + w;

    WCtx C;
    load_wctx(C, l, Wih, Whh, bih, bhh);

    int o0 = l;
    int o1 = (l < 4) ? (l + 32) : 35;
    ull wf0[10], wf1[10];
#pragma unroll
    for (int i = 0; i < 10; i++) {
        wf0[i] = pk2(Wfc[o0 * HH + 2 * i], Wfc[o0 * HH + 2 * i + 1]);
        wf1[i] = pk2(Wfc[o1 * HH + 2 * i], Wfc[o1 * HH + 2 * i + 1]);
    }
    float bo0 = bfc[o0], bo1 = bfc[o1];

    float* xb_ = &xbuf[w][0][0];
    float* hb_ = &hbuf[w][0][0];
    float* orow = out_xs + (size_t)b * SS * FF;

    float h = (l < HH) ? g_h[b * HH + l] : 0.f;
    if (l < HH) hb_[l] = h;
    __syncwarp();

    auto proj = [&](const float* hsrc, float* xdst, int so) {
        ull a0a = 0, a0b = 0, a1a = 0, a1b = 0;
        const ulonglong2* hv = reinterpret_cast<const ulonglong2*>(hsrc);
#pragma unroll
        for (int i = 0; i < 5; i++) {
            ulonglong2 v = hv[i];
            a0a = fma2(wf0[2 * i], v.x, a0a);
            a0b = fma2(wf0[2 * i + 1], v.y, a0b);
            a1a = fma2(wf1[2 * i], v.x, a1a);
            a1b = fma2(wf1[2 * i + 1], v.y, a1b);
        }
        float x0 = tanh_hw(hadd2(add2(a0a, a0b)) + bo0);
        float x1 = tanh_hw(hadd2(add2(a1a, a1b)) + bo1);
        float* og = orow + (size_t)so * FF;
        og[o0] = x0;
        xdst[o0] = x0;
        if (l < 4) { og[32 + l] = x1; xdst[32 + l] = x1; }
        __syncwarp();
    };

    proj(hb_, xb_, SS - 1);

    for (int st = 1; st < SS; ++st) {
        int cur = (st - 1) & 1, nxt = cur ^ 1;
        float hn = gru_cell_w(C, xb_ + cur * FF, hb_ + cur * HH, h);
        hn = tanh_hw(hn);
        if (l < HH) { h = hn; hb_[nxt * HH + l] = hn; }
        __syncwarp();
        proj(hb_ + nxt * HH, xb_ + nxt * FF, SS - 1 - st);
    }
}

// ---------------------------------------------------------------------------
extern "C" void kernel_launch(void* const* d_in, const int* in_sizes, int n_in,
                              void* d_out, int out_size) {
    const float* x = (const float*)d_in[0];
    const int* oh = (const int*)d_in[1];
    const float* e0 = (const float*)d_in[2];
    const float* e1 = (const float*)d_in[3];
    const float* e2 = (const float*)d_in[4];
    const float* e3 = (const float*)d_in[5];
    const float* Wih1 = (const float*)d_in[6];
    const float* Whh1 = (const float*)d_in[7];
    const float* bih1 = (const float*)d_in[8];
    const float* bhh1 = (const float*)d_in[9];
    const float* Wih2 = (const float*)d_in[10];
    const float* Whh2 = (const float*)d_in[11];
    const float* bih2 = (const float*)d_in[12];
    const float* bhh2 = (const float*)d_in[13];
    const float* Wfc = (const float*)d_in[14];
    const float* bfc = (const float*)d_in[15];

    float* out = (float*)d_out;
    float* origin = out;                          // (B,S,F)
    float* xs = out + (size_t)BB * SS * FF;       // (B,S,F) flipped decode

    detect_kernel<<<1, 32>>>(oh);
    embed_kernel<<<(BB * SS + 255) / 256, 256>>>(x, oh, e0, e1, e2, e3, origin);
    encoder_kernel<<<BB / 8, 256>>>(origin, Wih1, Whh1, bih1, bhh1);
    decoder_kernel<<<BB / 8, 256>>>(Wih2, Whh2, bih2, bhh2, Wfc, bfc, xs);
}

// round 15
// speedup vs baseline: 1.6415x; 1.6415x over previous
#include <cuda_runtime.h>
#include <cstdint>
#include <cstddef>

#define BB 1024
#define SS 1024
#define FF 36
#define HH 20
#define FULLMASK 0xffffffffu

typedef unsigned long long ull;

__device__ float g_h[BB * HH];
__device__ int g_oh64;

// ---------------------------------------------------------------------------
// f32x2 packed helpers (packing = 2 adjacent K-elements of one batch)
// ---------------------------------------------------------------------------
__device__ __forceinline__ ull fma2(ull a, ull b, ull c) {
    ull d; asm("fma.rn.f32x2 %0,%1,%2,%3;" : "=l"(d) : "l"(a), "l"(b), "l"(c)); return d;
}
__device__ __forceinline__ ull pk2(float a, float b) {
    ull r; asm("mov.b64 %0,{%1,%2};" : "=l"(r) : "f"(a), "f"(b)); return r;
}
__device__ __forceinline__ float hadd2(ull v) {
    float lo, hi; asm("mov.b64 {%0,%1},%2;" : "=f"(lo), "=f"(hi) : "l"(v));
    return lo + hi;
}
__device__ __forceinline__ float tanh_hw(float x) {
    float y; asm("tanh.approx.f32 %0,%1;" : "=f"(y) : "f"(x)); return y;
}
__device__ __forceinline__ void cpasync16(uint32_t saddr, const void* g) {
    asm volatile("cp.async.cg.shared.global [%0], [%1], 16;" :: "r"(saddr), "l"(g));
}
#define CP_COMMIT() asm volatile("cp.async.commit_group;" ::: "memory")
#define CP_WAIT3()  asm volatile("cp.async.wait_group 3;" ::: "memory")

// ---------------------------------------------------------------------------
__global__ void detect_kernel(const int* __restrict__ oh) {
    if (threadIdx.x == 0 && blockIdx.x == 0) {
        int z = 1;
        for (int i = 1; i < 64; i += 2)
            if (oh[i] != 0) { z = 0; break; }
        g_oh64 = z;
    }
}

__global__ void embed_kernel(const float* __restrict__ x,
                             const int* __restrict__ oh,
                             const float* __restrict__ e0,
                             const float* __restrict__ e1,
                             const float* __restrict__ e2,
                             const float* __restrict__ e3,
                             float* __restrict__ origin) {
    int idx = blockIdx.x * blockDim.x + threadIdx.x;
    if (idx >= BB * SS) return;
    int i0, i1, i2, i3;
    if (g_oh64) {
        const int* p = oh + (size_t)idx * 8;
        i0 = p[0]; i1 = p[2]; i2 = p[4]; i3 = p[6];
    } else {
        int4 o = reinterpret_cast<const int4*>(oh)[idx];
        i0 = o.x; i1 = o.y; i2 = o.z; i3 = o.w;
    }
    const float4* xr = reinterpret_cast<const float4*>(x + (size_t)idx * 12);
    float4* out = reinterpret_cast<float4*>(origin + (size_t)idx * FF);
    out[0] = xr[0];
    out[1] = xr[1];
    out[2] = xr[2];
    out[3] = reinterpret_cast<const float4*>(e0)[i0];
    out[4] = reinterpret_cast<const float4*>(e1)[i1];
    const float4* e2p = reinterpret_cast<const float4*>(e2);
    out[5] = e2p[i2 * 2];
    out[6] = e2p[i2 * 2 + 1];
    const float4* e3p = reinterpret_cast<const float4*>(e3);
    out[7] = e3p[i3 * 2];
    out[8] = e3p[i3 * 2 + 1];
}

// ---------------------------------------------------------------------------
// Warp-per-batch GRU, same-unit mapping (critical-path shfls removed):
//   lanes 0..19 : slot0 = r row u (=l), slot1 = n row 40+u  -> r,n LOCAL
//   lanes 20..31: slot0 = z rows 20..31 (units 0..11)
//   lanes 20..27: slot1 = z rows 32..39 (units 12..19)
// Single accumulator per dot-slot (as in R12; split accumulators regressed).
// ---------------------------------------------------------------------------
struct WCtx {
    ull wx0[18], wx1[18];
    ull wh0[10], wh1[10];
    float b0c;          // slot0 combined bias (sigmoid rows)
    float b1i, b1h, ka; // slot1: arg = ka*(sx1 + r*(sh1+b1h) + b1i)
    bool isH;
    int l;
};

__device__ __forceinline__ void load_wctx(
    WCtx& C, int l,
    const float* __restrict__ Wih, const float* __restrict__ Whh,
    const float* __restrict__ bih, const float* __restrict__ bhh) {
    C.l = l;
    C.isH = (l < HH);
    int r0 = l;                                              // rows 0..31
    int r1 = C.isH ? (40 + l) : ((l < 28) ? (l + 12) : 59);  // n rows / z rows 32..39
#pragma unroll
    for (int i = 0; i < 18; i++) {
        C.wx0[i] = pk2(Wih[r0 * FF + 2 * i], Wih[r0 * FF + 2 * i + 1]);
        C.wx1[i] = pk2(Wih[r1 * FF + 2 * i], Wih[r1 * FF + 2 * i + 1]);
    }
#pragma unroll
    for (int i = 0; i < 10; i++) {
        C.wh0[i] = pk2(Whh[r0 * HH + 2 * i], Whh[r0 * HH + 2 * i + 1]);
        C.wh1[i] = pk2(Whh[r1 * HH + 2 * i], Whh[r1 * HH + 2 * i + 1]);
    }
    C.b0c = bih[r0] + bhh[r0];
    if (C.isH) { C.b1i = bih[r1]; C.b1h = bhh[r1]; C.ka = 1.0f; }
    else       { C.b1i = bih[r1] + bhh[r1]; C.b1h = 0.f; C.ka = 0.5f; }
}

// One GRU cell: x-dot + h-dot from per-warp smem. Returns raw new h (l<20).
__device__ __forceinline__ float gru_cell_w(
    const WCtx& C, const float* __restrict__ xs, const float* __restrict__ hs,
    float hprev) {
    ull ax0 = 0, ax1 = 0, ah0 = 0, ah1 = 0;
    const ulonglong2* xv = reinterpret_cast<const ulonglong2*>(xs);
#pragma unroll
    for (int i = 0; i < 9; i++) {
        ulonglong2 v = xv[i];
        ax0 = fma2(C.wx0[2 * i], v.x, ax0);
        ax0 = fma2(C.wx0[2 * i + 1], v.y, ax0);
        ax1 = fma2(C.wx1[2 * i], v.x, ax1);
        ax1 = fma2(C.wx1[2 * i + 1], v.y, ax1);
    }
    const ulonglong2* hv = reinterpret_cast<const ulonglong2*>(hs);
#pragma unroll
    for (int i = 0; i < 5; i++) {
        ulonglong2 v = hv[i];
        ah0 = fma2(C.wh0[2 * i], v.x, ah0);
        ah0 = fma2(C.wh0[2 * i + 1], v.y, ah0);
        ah1 = fma2(C.wh1[2 * i], v.x, ah1);
        ah1 = fma2(C.wh1[2 * i + 1], v.y, ah1);
    }
    float sx0 = hadd2(ax0), sh0 = hadd2(ah0);
    float sx1 = hadd2(ax1), sh1 = hadd2(ah1);
    // slot0: sigmoid (r local for lanes<20; z rows 20..31 on lanes 20..31)
    float sig0 = fmaf(0.5f, tanh_hw(0.5f * (sx0 + sh0 + C.b0c)), 0.5f);
    // slot1: n with LOCAL r (lanes<20); z rows 32..39 (lanes 20..27, r:=1)
    float r_ = C.isH ? sig0 : 1.0f;
    float t1 = tanh_hw(C.ka * (sx1 + fmaf(r_, sh1 + C.b1h, C.b1i)));
    float val1 = C.isH ? t1 : fmaf(0.5f, t1, 0.5f);
    // z gather (unit u = l < 20): overlaps the local r->n chain
    float zA = __shfl_sync(FULLMASK, sig0, (20 + C.l) & 31);  // z row 20+u, u<12
    float zB = __shfl_sync(FULLMASK, val1, (8 + C.l) & 31);   // z row 20+u, u>=12
    float z = (C.l < 12) ? zA : zB;
    return fmaf(z, hprev - val1, val1);   // val1 = n (local) on h-lanes
}

// ---------------------------------------------------------------------------
// Encoder: warp per batch (8 warps/CTA); 4-slot x ring fed by cp.async
// (3 groups in flight).
// ---------------------------------------------------------------------------
__global__ void __launch_bounds__(256, 1) encoder_kernel(
    const float* __restrict__ xin,
    const float* __restrict__ Wih, const float* __restrict__ Whh,
    const float* __restrict__ bih, const float* __restrict__ bhh) {
    __shared__ __align__(16) float xring[8][4][FF];
    __shared__ __align__(16) float hbuf[8][2][HH];

    int tid = threadIdx.x;
    int w = tid >> 5, l = tid & 31;
    int b = blockIdx.x * 8 + w;

    WCtx C;
    load_wctx(C, l, Wih, Whh, bih, bhh);

    const float* xrow = xin + (size_t)b * SS * FF;
    float* xr_ = &xring[w][0][0];
    float* hb_ = &hbuf[w][0][0];
    uint32_t xr_s = (uint32_t)__cvta_generic_to_shared(xr_);

    bool ld = (l < 9);
#pragma unroll
    for (int s0 = 0; s0 < 3; s0++) {
        if (ld) cpasync16(xr_s + (uint32_t)(s0 * FF + l * 4) * 4,
                          xrow + (size_t)s0 * FF + l * 4);
        CP_COMMIT();
    }
    if (l < HH) hb_[l] = 0.f;

    float h = 0.f;
    for (int s = 0; s < SS; ++s) {
        if (ld && (s + 3 < SS))
            cpasync16(xr_s + (uint32_t)(((s + 3) & 3) * FF + l * 4) * 4,
                      xrow + (size_t)(s + 3) * FF + l * 4);
        CP_COMMIT();
        CP_WAIT3();          // group for slot s complete
        __syncwarp();
        int cur = s & 1;
        float hn = gru_cell_w(C, xr_ + (s & 3) * FF, hb_ + cur * HH, h);
        if (l < HH) { h = hn; hb_[(cur ^ 1) * HH + l] = hn; }
        __syncwarp();
    }
    if (l < HH) g_h[b * HH + l] = tanh_hw(h);
}

// ---------------------------------------------------------------------------
// Decoder: warp per batch (8 warps/CTA); gates -> tanh -> proj.
// proj: slot0 o=l (0..31), slot1 o=l+32 (l<4); Wfc rows K-packed in regs.
// ---------------------------------------------------------------------------
__global__ void __launch_bounds__(256, 1) decoder_kernel(
    const float* __restrict__ Wih, const float* __restrict__ Whh,
    const float* __restrict__ bih, const float* __restrict__ bhh,
    const float* __restrict__ Wfc, const float* __restrict__ bfc,
    float* __restrict__ out_xs) {
    __shared__ __align__(16) float xbuf[8][2][FF];
    __shared__ __align__(16) float hbuf[8][2][HH];

    int tid = threadIdx.x;
    int w = tid >> 5, l = tid & 31;
    int b = blockIdx.x * 8 + w;

    WCtx C;
    load_wctx(C, l, Wih, Whh, bih, bhh);

    int o0 = l;
    int o1 = (l < 4) ? (l + 32) : 35;
    ull wf0[10], wf1[10];
#pragma unroll
    for (int i = 0; i < 10; i++) {
        wf0[i] = pk2(Wfc[o0 * HH + 2 * i], Wfc[o0 * HH + 2 * i + 1]);
        wf1[i] = pk2(Wfc[o1 * HH + 2 * i], Wfc[o1 * HH + 2 * i + 1]);
    }
    float bo0 = bfc[o0], bo1 = bfc[o1];

    float* xb_ = &xbuf[w][0][0];
    float* hb_ = &hbuf[w][0][0];
    float* orow = out_xs + (size_t)b * SS * FF;

    float h = (l < HH) ? g_h[b * HH + l] : 0.f;
    if (l < HH) hb_[l] = h;
    __syncwarp();

    auto proj = [&](const float* hsrc, float* xdst, int so) {
        ull a0 = 0, a1 = 0;
        const ulonglong2* hv = reinterpret_cast<const ulonglong2*>(hsrc);
#pragma unroll
        for (int i = 0; i < 5; i++) {
            ulonglong2 v = hv[i];
            a0 = fma2(wf0[2 * i], v.x, a0);
            a0 = fma2(wf0[2 * i + 1], v.y, a0);
            a1 = fma2(wf1[2 * i], v.x, a1);
            a1 = fma2(wf1[2 * i + 1], v.y, a1);
        }
        float x0 = tanh_hw(hadd2(a0) + bo0);
        float x1 = tanh_hw(hadd2(a1) + bo1);
        float* og = orow + (size_t)so * FF;
        og[o0] = x0;
        xdst[o0] = x0;
        if (l < 4) { og[32 + l] = x1; xdst[32 + l] = x1; }
        __syncwarp();
    };

    proj(hb_, xb_, SS - 1);

    for (int st = 1; st < SS; ++st) {
        int cur = (st - 1) & 1, nxt = cur ^ 1;
        float hn = gru_cell_w(C, xb_ + cur * FF, hb_ + cur * HH, h);
        hn = tanh_hw(hn);
        if (l < HH) { h = hn; hb_[nxt * HH + l] = hn; }
        __syncwarp();
        proj(hb_ + nxt * HH, xb_ + nxt * FF, SS - 1 - st);
    }
}

// ---------------------------------------------------------------------------
extern "C" void kernel_launch(void* const* d_in, const int* in_sizes, int n_in,
                              void* d_out, int out_size) {
    const float* x = (const float*)d_in[0];
    const int* oh = (const int*)d_in[1];
    const float* e0 = (const float*)d_in[2];
    const float* e1 = (const float*)d_in[3];
    const float* e2 = (const float*)d_in[4];
    const float* e3 = (const float*)d_in[5];
    const float* Wih1 = (const float*)d_in[6];
    const float* Whh1 = (const float*)d_in[7];
    const float* bih1 = (const float*)d_in[8];
    const float* bhh1 = (const float*)d_in[9];
    const float* Wih2 = (const float*)d_in[10];
    const float* Whh2 = (const float*)d_in[11];
    const float* bih2 = (const float*)d_in[12];
    const float* bhh2 = (const float*)d_in[13];
    const float* Wfc = (const float*)d_in[14];
    const float* bfc = (const float*)d_in[15];

    float* out = (float*)d_out;
    float* origin = out;                          // (B,S,F)
    float* xs = out + (size_t)BB * SS * FF;       // (B,S,F) flipped decode

    detect_kernel<<<1, 32>>>(oh);
    embed_kernel<<<(BB * SS + 255) / 256, 256>>>(x, oh, e0, e1, e2, e3, origin);
    encoder_kernel<<<BB / 8, 256>>>(origin, Wih1, Whh1, bih1, bhh1);
    decoder_kernel<<<BB / 8, 256>>>(Wih2, Whh2, bih2, bhh2, Wfc, bfc, xs);
}